// round 1
// baseline (speedup 1.0000x reference)
#include <cuda_runtime.h>
#include <cstddef>

#define NSTEPS 16
#define BMAX   131072
#define TPB    256
// smem: v[64][TPB], U[64][TPB], acc[64][TPB], + 4 const 8x8 matrices
#define SMEM_FLOATS (3*64*TPB + 4*64)
#define SMEM_BYTES  (SMEM_FLOATS*4)

// Per-batch folded Z matrix (36 sym-folded entries), transposed [m*B + b]
__device__ float g_Zf[36 * BMAX];

__device__ __forceinline__ constexpr int fidx(int i, int j) {
    // upper-triangle (i<j) linear index, 0..27
    return i*8 - i*(i+1)/2 + (j - i - 1);
}

// ---------------------------------------------------------------------------
// Precompute per-batch constant:  Z_b = C W2 - W2 C,  C = v^T v  (v = eps[b])
// Stored folded for symmetric contraction with S = U^T U:
//   m(i,i) -> Z_ii ,  m(i<j) -> Z_ij + Z_ji
// Using W2a = W2 - W2^T:
//   Z_ii        = - sum_k C_ik * W2a_ik
//   Z_ij + Z_ji = - sum_k ( C_ik * W2a_jk + C_jk * W2a_ik )
// ---------------------------------------------------------------------------
__global__ void precompute_kernel(const float* __restrict__ eps,
                                  const float* __restrict__ W2, int B) {
    int b = blockIdx.x * blockDim.x + threadIdx.x;
    if (b >= B) return;

    float v[64];
    const float4* vp = reinterpret_cast<const float4*>(eps + (size_t)b * 64);
#pragma unroll
    for (int i = 0; i < 16; i++) {
        float4 t = __ldg(vp + i);
        v[4*i+0] = t.x; v[4*i+1] = t.y; v[4*i+2] = t.z; v[4*i+3] = t.w;
    }

    // C = v^T v (symmetric, store full for easy indexing)
    float C[8][8];
#pragma unroll
    for (int i = 0; i < 8; i++) {
#pragma unroll
        for (int j = i; j < 8; j++) {
            float s = 0.f;
#pragma unroll
            for (int k = 0; k < 8; k++) s = fmaf(v[k*8+i], v[k*8+j], s);
            C[i][j] = s; C[j][i] = s;
        }
    }

    float w2a[8][8];
#pragma unroll
    for (int i = 0; i < 8; i++)
#pragma unroll
        for (int j = 0; j < 8; j++)
            w2a[i][j] = __ldg(W2 + i*8 + j) - __ldg(W2 + j*8 + i);

    int m = 0;
#pragma unroll
    for (int i = 0; i < 8; i++) {
#pragma unroll
        for (int j = i; j < 8; j++) {
            float s = 0.f;
            if (i == j) {
#pragma unroll
                for (int k = 0; k < 8; k++) s -= C[i][k] * w2a[i][k];
            } else {
#pragma unroll
                for (int k = 0; k < 8; k++)
                    s -= C[i][k] * w2a[j][k] + C[j][k] * w2a[i][k];
            }
            g_Zf[(size_t)m * B + b] = s;
            m++;
        }
    }
}

// ---------------------------------------------------------------------------
// Main flow kernel: one thread = one batch element.
//   vel  = F U,  F = antisym(W0 + t W1 + (U W2) U^T)
//   rate = 0.5 * ( <U^T U, Zf_b> + sum_ab Q_ab (Q W2a)_ba ),  Q = v^T U
// RK4 with 16 steps. U_base / acc / v live in shared memory (transposed
// layout [idx][tid] for conflict-free access).
// ---------------------------------------------------------------------------
__global__ __launch_bounds__(TPB, 1)
void flow_kernel(const float* __restrict__ U0, const float* __restrict__ eps,
                 const float* __restrict__ W0, const float* __restrict__ W1,
                 const float* __restrict__ W2, float* __restrict__ out, int B) {
    extern __shared__ float smem[];
    const int tid = threadIdx.x;
    float* sv   = smem;                 // [64][TPB]
    float* sU   = smem + 64 * TPB;      // [64][TPB]  U_base (= U_n)
    float* sacc = smem + 2 * 64 * TPB;  // [64][TPB]  running U_{n+1}
    float* cw2  = smem + 3 * 64 * TPB;  // [64]
    float* cw2a = cw2  + 64;
    float* cw0a = cw2a + 64;
    float* cw1a = cw0a + 64;

    if (tid < 64) {
        int i = tid >> 3, j = tid & 7;
        cw2[tid]  = W2[tid];
        cw2a[tid] = W2[i*8+j] - W2[j*8+i];
        cw0a[tid] = 0.5f * (W0[i*8+j] - W0[j*8+i]);
        cw1a[tid] = 0.5f * (W1[i*8+j] - W1[j*8+i]);
    }

    int b = blockIdx.x * TPB + tid;
    bool active = (b < B);
    int bb = active ? b : 0;

#pragma unroll
    for (int idx = 0; idx < 64; idx++) {
        float u = U0[(size_t)bb * 64 + idx];
        sU[idx*TPB + tid]   = u;
        sacc[idx*TPB + tid] = u;
        sv[idx*TPB + tid]   = eps[(size_t)bb * 64 + idx];
    }
    __syncthreads();

    float Us[64];
#pragma unroll
    for (int idx = 0; idx < 64; idx++) Us[idx] = sU[idx*TPB + tid];
    float lj = 0.f;
    const float dt = 1.0f / NSTEPS;
    const float* zf = g_Zf + bb;

#pragma unroll 1
    for (int n = 0; n < NSTEPS; n++) {
        float tn = (float)n * dt;
#pragma unroll 1
        for (int s = 0; s < 4; s++) {
            float ts = tn + ((s == 0) ? 0.f : ((s == 3) ? dt : 0.5f * dt));

            // A = Us * W2
            float A[64];
#pragma unroll
            for (int i = 0; i < 8; i++) {
#pragma unroll
                for (int j = 0; j < 8; j++) {
                    float a = 0.f;
#pragma unroll
                    for (int k = 0; k < 8; k++)
                        a = fmaf(Us[i*8+k], cw2[k*8+j], a);
                    A[i*8+j] = a;
                }
            }

            // F upper triangle: F_ij = W0a_ij + t*W1a_ij + 0.5*(A_i.Us_j - A_j.Us_i)
            float Fv[28];
#pragma unroll
            for (int i = 0; i < 8; i++) {
#pragma unroll
                for (int j = i + 1; j < 8; j++) {
                    float d = 0.f;
#pragma unroll
                    for (int k = 0; k < 8; k++)
                        d += A[i*8+k] * Us[j*8+k] - A[j*8+k] * Us[i*8+k];
                    Fv[fidx(i, j)] = fmaf(ts, cw1a[i*8+j], cw0a[i*8+j]) + 0.5f * d;
                }
            }

            // Q = v^T Us  (stream v rows from smem)
            float Q[64];
#pragma unroll
            for (int x = 0; x < 64; x++) Q[x] = 0.f;
#pragma unroll
            for (int k = 0; k < 8; k++) {
                float vk[8];
#pragma unroll
                for (int i = 0; i < 8; i++) vk[i] = sv[(k*8+i)*TPB + tid];
#pragma unroll
                for (int i = 0; i < 8; i++)
#pragma unroll
                    for (int j = 0; j < 8; j++)
                        Q[i*8+j] = fmaf(vk[i], Us[k*8+j], Q[i*8+j]);
            }

            // r2 = sum_ab Q_ab (Q W2a)_ba
            float r2 = 0.f;
#pragma unroll
            for (int bq = 0; bq < 8; bq++) {
#pragma unroll
                for (int a = 0; a < 8; a++) {
                    float t_ = 0.f;
#pragma unroll
                    for (int c = 0; c < 8; c++) {
                        if (c == a) continue;
                        t_ = fmaf(Q[bq*8+c], cw2a[c*8+a], t_);
                    }
                    r2 = fmaf(Q[a*8+bq], t_, r2);
                }
            }

            // r1 = <U^T U, Zf> (folded symmetric)
            float r1 = 0.f;
            {
                int m = 0;
#pragma unroll
                for (int i = 0; i < 8; i++) {
#pragma unroll
                    for (int j = i; j < 8; j++) {
                        float sij = 0.f;
#pragma unroll
                        for (int k = 0; k < 8; k++)
                            sij = fmaf(Us[k*8+i], Us[k*8+j], sij);
                        r1 = fmaf(sij, __ldg(zf + (size_t)m * B), r1);
                        m++;
                    }
                }
            }
            float rate = 0.5f * (r1 + r2);

            // vel = F * Us (F antisymmetric, diag 0)
            float vel[64];
#pragma unroll
            for (int i = 0; i < 8; i++) {
#pragma unroll
                for (int j = 0; j < 8; j++) {
                    float sm_ = 0.f;
#pragma unroll
                    for (int k = 0; k < 8; k++) {
                        if (k == i) continue;
                        if (k > i) sm_ = fmaf( Fv[fidx(i, k)], Us[k*8+j], sm_);
                        else       sm_ = fmaf(-Fv[fidx(k, i)], Us[k*8+j], sm_);
                    }
                    vel[i*8+j] = sm_;
                }
            }

            // RK4 combine
            float w = dt * ((s == 0 || s == 3) ? (1.f/6.f) : (1.f/3.f));
            lj = fmaf(w, rate, lj);
            float cc = (s == 2) ? dt : 0.5f * dt;
#pragma unroll
            for (int idx = 0; idx < 64; idx++) {
                float a_ = fmaf(w, vel[idx], sacc[idx*TPB + tid]);
                sacc[idx*TPB + tid] = a_;
                Us[idx] = (s < 3) ? fmaf(cc, vel[idx], sU[idx*TPB + tid]) : a_;
            }
        }
        // U_{n+1} into U_base for next step (sacc already holds it)
#pragma unroll
        for (int idx = 0; idx < 64; idx++) sU[idx*TPB + tid] = Us[idx];
    }

    if (active) {
#pragma unroll
        for (int idx = 0; idx < 64; idx++)
            out[(size_t)b * 64 + idx] = Us[idx];
        out[(size_t)B * 64 + b] = lj;
    }
}

extern "C" void kernel_launch(void* const* d_in, const int* in_sizes, int n_in,
                              void* d_out, int out_size) {
    const float* U0  = (const float*)d_in[0];
    const float* eps = (const float*)d_in[1];
    const float* W0  = (const float*)d_in[2];
    const float* W1  = (const float*)d_in[3];
    const float* W2  = (const float*)d_in[4];
    float* out = (float*)d_out;

    int B = in_sizes[0] / 64;
    if (B > BMAX) B = BMAX;

    cudaFuncSetAttribute(flow_kernel,
                         cudaFuncAttributeMaxDynamicSharedMemorySize, SMEM_BYTES);

    int grid = (B + TPB - 1) / TPB;
    precompute_kernel<<<grid, TPB>>>(eps, W2, B);
    flow_kernel<<<grid, TPB, SMEM_BYTES>>>(U0, eps, W0, W1, W2, out, B);
}

// round 2
// speedup vs baseline: 1.2326x; 1.2326x over previous
#include <cuda_runtime.h>
#include <cstddef>

#define NSTEPS 16
#define BMAX   131072
#define TPB    256

typedef unsigned long long ull;

// Per-batch folded Z weights for the 20 (i, jpair) S-pairs, layout (p*B + b) ull pairs
__device__ float g_Zw[40 * BMAX];

// ---------------- f32x2 helpers ----------------
__device__ __forceinline__ ull f2fma(ull a, ull b, ull c) {
    ull d;
    asm("fma.rn.f32x2 %0, %1, %2, %3;" : "=l"(d) : "l"(a), "l"(b), "l"(c));
    return d;
}
__device__ __forceinline__ ull dupf(float s) {
    ull d; asm("mov.b64 %0, {%1, %1};" : "=l"(d) : "f"(s)); return d;
}
__device__ __forceinline__ ull dup_lo(ull p) {
    ull d;
    asm("{\n\t.reg .f32 l,h;\n\tmov.b64 {l,h}, %1;\n\tmov.b64 %0, {l,l};\n\t}"
        : "=l"(d) : "l"(p));
    return d;
}
__device__ __forceinline__ ull dup_hi(ull p) {
    ull d;
    asm("{\n\t.reg .f32 l,h;\n\tmov.b64 {l,h}, %1;\n\tmov.b64 %0, {h,h};\n\t}"
        : "=l"(d) : "l"(p));
    return d;
}
__device__ __forceinline__ float get_lo(ull p) {
    float l, h; asm("mov.b64 {%0, %1}, %2;" : "=f"(l), "=f"(h) : "l"(p)); return l;
}
__device__ __forceinline__ float get_hi(ull p) {
    float l, h; asm("mov.b64 {%0, %1}, %2;" : "=f"(l), "=f"(h) : "l"(p)); return h;
}
__device__ __forceinline__ float hadd(ull p) {
    float l, h; asm("mov.b64 {%0, %1}, %2;" : "=f"(l), "=f"(h) : "l"(p)); return l + h;
}
__device__ __forceinline__ ull pack2(float a, float b) {
    ull d; asm("mov.b64 %0, {%1, %2};" : "=l"(d) : "f"(a), "f"(b)); return d;
}

__device__ __forceinline__ constexpr int fidx(int i, int j) {
    return i * 8 - i * (i + 1) / 2 + (j - i - 1);
}

// smem layout (bytes):
//   sUb   : ull [32*TPB]            (64KB)   U_base packed pairs [pair][tid]
//   sacc  : ull [32*TPB]            (64KB)   RK4 accumulator packed
//   cW2p  : ull [32]                         W2 row pairs
//   cW2aT : ull [32]                         rows of W2a^T as pairs
//   sv    : float [64*TPB]          (64KB)   eps scalar [idx][tid]
//   cw0a  : float [64], cw1a: float [64]
#define SMEM_BYTES (32*TPB*8*2 + 64*8 + 64*TPB*4 + 128*4)

// ---------------------------------------------------------------------------
// Precompute per-batch Z weights:
//   Z = C W2 - W2 C, C = v^T v.  Folded weight w(i,j):
//     j>i : Z_ij + Z_ji = -sum_k (C_ik W2a_jk + C_jk W2a_ik)
//     j==i: Z_ii        = -sum_k  C_ik W2a_ik
//     j<i : 0
//   Stored for the 20 (i, jpair) pairs with jpair >= i/2, pair p -> (w(i,2jj), w(i,2jj+1))
// ---------------------------------------------------------------------------
__global__ void precompute_kernel(const float* __restrict__ eps,
                                  const float* __restrict__ W2, int B) {
    int b = blockIdx.x * blockDim.x + threadIdx.x;
    if (b >= B) return;

    float v[64];
    const float4* vp = reinterpret_cast<const float4*>(eps + (size_t)b * 64);
#pragma unroll
    for (int i = 0; i < 16; i++) {
        float4 t = __ldg(vp + i);
        v[4*i+0] = t.x; v[4*i+1] = t.y; v[4*i+2] = t.z; v[4*i+3] = t.w;
    }

    float C[8][8];
#pragma unroll
    for (int i = 0; i < 8; i++) {
#pragma unroll
        for (int j = i; j < 8; j++) {
            float s = 0.f;
#pragma unroll
            for (int k = 0; k < 8; k++) s = fmaf(v[k*8+i], v[k*8+j], s);
            C[i][j] = s; C[j][i] = s;
        }
    }

    float w2a[8][8];
#pragma unroll
    for (int i = 0; i < 8; i++)
#pragma unroll
        for (int j = 0; j < 8; j++)
            w2a[i][j] = __ldg(W2 + i*8 + j) - __ldg(W2 + j*8 + i);

    int p = 0;
#pragma unroll
    for (int i = 0; i < 8; i++) {
#pragma unroll
        for (int jj = 0; jj < 4; jj++) {
            if (jj < i / 2) continue;
            float wpair[2];
#pragma unroll
            for (int h = 0; h < 2; h++) {
                int j = 2*jj + h;
                float s = 0.f;
                if (j > i) {
#pragma unroll
                    for (int k = 0; k < 8; k++)
                        s -= C[i][k] * w2a[j][k] + C[j][k] * w2a[i][k];
                } else if (j == i) {
#pragma unroll
                    for (int k = 0; k < 8; k++) s -= C[i][k] * w2a[i][k];
                }
                wpair[h] = s;
            }
            g_Zw[((size_t)p * B + b) * 2 + 0] = wpair[0];
            g_Zw[((size_t)p * B + b) * 2 + 1] = wpair[1];
            p++;
        }
    }
}

// ---------------------------------------------------------------------------
// Main flow kernel: one thread per batch element, matrices packed as f32x2
// column pairs so the FFMA2 (fma.rn.f32x2) pipe does 2 flops per issue slot.
// ---------------------------------------------------------------------------
__global__ __launch_bounds__(TPB, 1)
void flow_kernel(const float* __restrict__ U0, const float* __restrict__ eps,
                 const float* __restrict__ W0, const float* __restrict__ W1,
                 const float* __restrict__ W2, float* __restrict__ out, int B) {
    extern __shared__ char smem_raw[];
    ull*   sUb   = reinterpret_cast<ull*>(smem_raw);
    ull*   sacc  = sUb + 32 * TPB;
    ull*   cW2p  = sacc + 32 * TPB;
    ull*   cW2aT = cW2p + 32;
    float* sv    = reinterpret_cast<float*>(cW2aT + 32);
    float* cw0a  = sv + 64 * TPB;
    float* cw1a  = cw0a + 64;

    const int tid = threadIdx.x;

    if (tid < 32) {
        int k = tid >> 2, cc = tid & 3;
        cW2p[tid]  = pack2(W2[k*8 + 2*cc], W2[k*8 + 2*cc + 1]);
        // W2a^T row a, element c = W2[c*8+a] - W2[a*8+c]
        int a = k;
        cW2aT[tid] = pack2(W2[(2*cc)*8 + a]   - W2[a*8 + 2*cc],
                           W2[(2*cc+1)*8 + a] - W2[a*8 + 2*cc + 1]);
    }
    if (tid < 64) {
        int i = tid >> 3, j = tid & 7;
        cw0a[tid] = 0.5f * (W0[i*8+j] - W0[j*8+i]);
        cw1a[tid] = 0.5f * (W1[i*8+j] - W1[j*8+i]);
    }

    int b = blockIdx.x * TPB + tid;
    bool active = (b < B);
    int bb = active ? b : 0;

    ull Us[32];
    {
        const ull* u0p = reinterpret_cast<const ull*>(U0) + (size_t)bb * 32;
#pragma unroll
        for (int p = 0; p < 32; p++) {
            ull u = __ldg(u0p + p);
            Us[p] = u;
            sUb[p*TPB + tid]  = u;
            sacc[p*TPB + tid] = u;
        }
#pragma unroll
        for (int idx = 0; idx < 64; idx++)
            sv[idx*TPB + tid] = eps[(size_t)bb * 64 + idx];
    }
    __syncthreads();

    float lj = 0.f;
    const float dt = 1.0f / NSTEPS;
    const ull* zw = reinterpret_cast<const ull*>(g_Zw) + bb;
    const ull NEG1 = dupf(-1.0f);
    const ull ZERO = 0ull;

#pragma unroll 1
    for (int n = 0; n < NSTEPS; n++) {
        float tn = (float)n * dt;
#pragma unroll 1
        for (int s = 0; s < 4; s++) {
            float ts = tn + ((s == 0) ? 0.f : ((s == 3) ? dt : 0.5f * dt));

            // ---- A = Us * W2 (packed along columns) ----
            ull A[32];
#pragma unroll
            for (int p = 0; p < 32; p++) A[p] = ZERO;
#pragma unroll
            for (int k = 0; k < 8; k++) {
                ull w0 = cW2p[k*4+0], w1 = cW2p[k*4+1], w2_ = cW2p[k*4+2], w3 = cW2p[k*4+3];
#pragma unroll
                for (int i = 0; i < 8; i++) {
                    ull u = (k & 1) ? dup_hi(Us[i*4 + (k>>1)]) : dup_lo(Us[i*4 + (k>>1)]);
                    A[i*4+0] = f2fma(u, w0, A[i*4+0]);
                    A[i*4+1] = f2fma(u, w1, A[i*4+1]);
                    A[i*4+2] = f2fma(u, w2_, A[i*4+2]);
                    A[i*4+3] = f2fma(u, w3, A[i*4+3]);
                }
            }

            // ---- F antisym: F_ij = w0a+ts*w1a + 0.5*(A_i.Us_j - A_j.Us_i) ----
            float F[64];
#pragma unroll
            for (int i = 0; i < 8; i++) {
#pragma unroll
                for (int j = i + 1; j < 8; j++) {
                    ull pacc = ZERO, qacc = ZERO;
#pragma unroll
                    for (int cc = 0; cc < 4; cc++) {
                        pacc = f2fma(A[i*4+cc], Us[j*4+cc], pacc);
                        qacc = f2fma(A[j*4+cc], Us[i*4+cc], qacc);
                    }
                    ull d2 = f2fma(qacc, NEG1, pacc);   // p - q
                    float dsum = hadd(d2);
                    float c01  = fmaf(ts, cw1a[i*8+j], cw0a[i*8+j]);
                    float f    = fmaf(0.5f, dsum, c01);
                    F[i*8+j] = f;
                    F[j*8+i] = -f;
                }
            }

            // ---- Q = v^T Us ----
            ull Q[32];
#pragma unroll
            for (int p = 0; p < 32; p++) Q[p] = ZERO;
#pragma unroll
            for (int k = 0; k < 8; k++) {
#pragma unroll
                for (int i = 0; i < 8; i++) {
                    ull vd = dupf(sv[(k*8+i)*TPB + tid]);
#pragma unroll
                    for (int cc = 0; cc < 4; cc++)
                        Q[i*4+cc] = f2fma(vd, Us[k*4+cc], Q[i*4+cc]);
                }
            }

            // ---- r2 = sum_ab Q_ab * (sum_c Q_bc W2a_ca), fully packed ----
            ull r2p0 = ZERO, r2p1 = ZERO;
#pragma unroll
            for (int a = 0; a < 8; a++) {
                ull wa0 = cW2aT[a*4+0], wa1 = cW2aT[a*4+1],
                    wa2 = cW2aT[a*4+2], wa3 = cW2aT[a*4+3];
#pragma unroll
                for (int bq = 0; bq < 8; bq++) {
                    ull t = f2fma(Q[bq*4+0], wa0, ZERO);
                    t = f2fma(Q[bq*4+1], wa1, t);
                    t = f2fma(Q[bq*4+2], wa2, t);
                    t = f2fma(Q[bq*4+3], wa3, t);
                    ull qd = (bq & 1) ? dup_hi(Q[a*4 + (bq>>1)]) : dup_lo(Q[a*4 + (bq>>1)]);
                    if (bq & 1) r2p1 = f2fma(qd, t, r2p1);
                    else        r2p0 = f2fma(qd, t, r2p0);
                }
            }

            // ---- S (20 triangle pairs) and r1 = <S, Zw> ----
            ull r1p = ZERO;
            {
                int p = 0;
#pragma unroll
                for (int i = 0; i < 8; i++) {
                    ull duds[8];
#pragma unroll
                    for (int k = 0; k < 8; k++)
                        duds[k] = (i & 1) ? dup_hi(Us[k*4 + (i>>1)]) : dup_lo(Us[k*4 + (i>>1)]);
#pragma unroll
                    for (int jj = 0; jj < 4; jj++) {
                        if (jj < i / 2) continue;
                        ull sacc_ = ZERO;
#pragma unroll
                        for (int k = 0; k < 8; k++)
                            sacc_ = f2fma(duds[k], Us[k*4+jj], sacc_);
                        ull z = __ldg(zw + (size_t)p * B);
                        r1p = f2fma(sacc_, z, r1p);
                        p++;
                    }
                }
            }
            float rate = 0.5f * (hadd(r1p) + hadd(r2p0) + hadd(r2p1));

            // ---- vel = F * Us ----
            ull vel[32];
#pragma unroll
            for (int i = 0; i < 8; i++) {
                ull v0 = ZERO, v1 = ZERO, v2_ = ZERO, v3 = ZERO;
#pragma unroll
                for (int k = 0; k < 8; k++) {
                    if (k == i) continue;
                    ull fd = dupf(F[i*8+k]);
                    v0 = f2fma(fd, Us[k*4+0], v0);
                    v1 = f2fma(fd, Us[k*4+1], v1);
                    v2_ = f2fma(fd, Us[k*4+2], v2_);
                    v3 = f2fma(fd, Us[k*4+3], v3);
                }
                vel[i*4+0] = v0; vel[i*4+1] = v1; vel[i*4+2] = v2_; vel[i*4+3] = v3;
            }

            // ---- RK4 combine ----
            float w = dt * ((s == 0 || s == 3) ? (1.f/6.f) : (1.f/3.f));
            lj = fmaf(w, rate, lj);
            ull wd = dupf(w);
            float cc_ = (s == 2) ? dt : 0.5f * dt;
            ull cd = dupf(cc_);
#pragma unroll
            for (int p = 0; p < 32; p++) {
                ull ac = f2fma(wd, vel[p], sacc[p*TPB + tid]);
                sacc[p*TPB + tid] = ac;
                Us[p] = (s < 3) ? f2fma(cd, vel[p], sUb[p*TPB + tid]) : ac;
            }
        }
#pragma unroll
        for (int p = 0; p < 32; p++) sUb[p*TPB + tid] = Us[p];
    }

    if (active) {
        ull* outp = reinterpret_cast<ull*>(out) + (size_t)b * 32;
#pragma unroll
        for (int p = 0; p < 32; p++) outp[p] = Us[p];
        out[(size_t)B * 64 + b] = lj;
    }
}

extern "C" void kernel_launch(void* const* d_in, const int* in_sizes, int n_in,
                              void* d_out, int out_size) {
    const float* U0  = (const float*)d_in[0];
    const float* eps = (const float*)d_in[1];
    const float* W0  = (const float*)d_in[2];
    const float* W1  = (const float*)d_in[3];
    const float* W2  = (const float*)d_in[4];
    float* out = (float*)d_out;

    int B = in_sizes[0] / 64;
    if (B > BMAX) B = BMAX;

    cudaFuncSetAttribute(flow_kernel,
                         cudaFuncAttributeMaxDynamicSharedMemorySize, SMEM_BYTES);

    int grid = (B + TPB - 1) / TPB;
    precompute_kernel<<<grid, TPB>>>(eps, W2, B);
    flow_kernel<<<grid, TPB, SMEM_BYTES>>>(U0, eps, W0, W1, W2, out, B);
}